// round 1
// baseline (speedup 1.0000x reference)
#include <cuda_runtime.h>
#include <cstdint>

// Problem constants (fixed by setup_inputs)
#define CC   256
#define LL   8192
#define BB   32
#define KCH  16          // K-chunk depth
#define TL   128         // positions per block

// Device scratch (allocation-free rule: __device__ globals)
__device__ __align__(16) unsigned long long g_Wd[CC * CC]; // Wd[c][o] = dup2(W[o][c]*inv[o])
__device__ float g_bias[CC];

// ---------------- helpers ----------------
__device__ __forceinline__ void cp16(uint32_t dst_smem, const void* src) {
    asm volatile("cp.async.cg.shared.global [%0], [%1], 16;\n"
                 :: "r"(dst_smem), "l"(src));
}
__device__ __forceinline__ unsigned long long fma2(unsigned long long a,
                                                   unsigned long long b,
                                                   unsigned long long c) {
    unsigned long long d;
    asm("fma.rn.f32x2 %0, %1, %2, %3;" : "=l"(d) : "l"(a), "l"(b), "l"(c));
    return d;
}
__device__ __forceinline__ float lo32(unsigned long long u) {
    return __uint_as_float((unsigned)(u & 0xffffffffull));
}
__device__ __forceinline__ float hi32(unsigned long long u) {
    return __uint_as_float((unsigned)(u >> 32));
}

// ---------------- pre-kernel: fold BN into W, dup-pack for f32x2 ----------------
__global__ void fold_kernel(const float* __restrict__ W, const float* __restrict__ b,
                            const float* __restrict__ gamma, const float* __restrict__ beta,
                            const float* __restrict__ mean, const float* __restrict__ var) {
    int c = blockIdx.x;    // input channel
    int o = threadIdx.x;   // output channel
    float inv = gamma[o] * rsqrtf(var[o] + 1e-5f);
    float w = W[o * CC + c] * inv;
    unsigned int bits = __float_as_uint(w);
    g_Wd[c * CC + o] = ((unsigned long long)bits << 32) | (unsigned long long)bits;
    if (c == 0) g_bias[o] = b[o] * inv + beta[o] - mean[o] * inv;
}

// ---------------- main fused kernel ----------------
// Block: 256 threads. Tile: 256 out-channels x 128 positions (one batch b).
// Thread microtile: 8 channels x 16 positions (64 f32x2 accumulators).
// smem layout (dynamic, 80 KiB):
//   [0      .. 32768)  Wbuf0: KCH x 256 dup-u64 (W' chunk)
//   [32768  .. 65536)  Wbuf1
//   [65536  .. 73728)  Xbuf0: 512 x 16B entries, interleaved [k][i][pg]
//   [73728  .. 81920)  Xbuf1
// Epilogue reuses offset 0 for the reduction scratch.
extern "C" __global__ void __launch_bounds__(256, 1)
caps_kernel(const float* __restrict__ x, float* __restrict__ out) {
    extern __shared__ char smem[];
    uint32_t sbase = (uint32_t)__cvta_generic_to_shared(smem);

    const int t  = threadIdx.x;
    const int b  = blockIdx.y;
    const int l0 = blockIdx.x * TL;
    const int cg = t >> 3;   // 0..31 : channels cg*8 .. cg*8+7
    const int pg = t & 7;    // 0..7  : positions pg*16 .. pg*16+15

    const float* xg = x + (size_t)b * CC * LL + l0;

    // ---- async copy of one K-chunk (kc) into buffer buf ----
    auto issue_copy = [&](int kc, int buf) {
        // W' chunk: 2048 x 16B, flat (g_Wd rows are contiguous in k)
        uint32_t wdst = sbase + buf * 32768;
        const char* wsrc = (const char*)(g_Wd + (size_t)kc * KCH * CC);
        #pragma unroll
        for (int r = 0; r < 8; r++) {
            int e = t + r * 256;
            cp16(wdst + e * 16, wsrc + e * 16);
        }
        // X chunk: 512 x 16B, interleaved dst: entry = (kk*4 + (c&3))*8 + (c>>2)
        uint32_t xdst = sbase + 65536 + buf * 8192;
        #pragma unroll
        for (int r = 0; r < 2; r++) {
            int e  = t + r * 256;
            int kk = e >> 5;
            int c  = e & 31;
            const float* src = xg + (size_t)(kc * KCH + kk) * LL + c * 4;
            int ent = (kk * 4 + (c & 3)) * 8 + (c >> 2);
            cp16(xdst + ent * 16, src);
        }
        asm volatile("cp.async.commit_group;\n");
    };

    unsigned long long acc[8][8];   // acc[i][q]: channel cg*8+i, positions pg*16+2q, +2q+1
    #pragma unroll
    for (int i = 0; i < 8; i++)
        #pragma unroll
        for (int q = 0; q < 8; q++) acc[i][q] = 0ull;

    issue_copy(0, 0);

    for (int kc = 0; kc < CC / KCH; kc++) {
        const int buf = kc & 1;
        if (kc < CC / KCH - 1) {
            issue_copy(kc + 1, buf ^ 1);
            asm volatile("cp.async.wait_group 1;\n");
        } else {
            asm volatile("cp.async.wait_group 0;\n");
        }
        __syncthreads();

        const ulonglong2* Wb = (const ulonglong2*)(smem + buf * 32768);
        const ulonglong2* Xb = (const ulonglong2*)(smem + 65536 + buf * 8192);

        #pragma unroll 4
        for (int k = 0; k < KCH; k++) {
            unsigned long long w2[8], x2[8];
            const ulonglong2* wr = Wb + k * 128 + cg * 4;  // 8 dup-channels
            #pragma unroll
            for (int i = 0; i < 4; i++) {
                ulonglong2 v = wr[i];
                w2[2 * i] = v.x; w2[2 * i + 1] = v.y;
            }
            const ulonglong2* xr = Xb + k * 32 + pg;       // 16 positions as 8 pairs
            #pragma unroll
            for (int i = 0; i < 4; i++) {
                ulonglong2 v = xr[i * 8];
                x2[2 * i] = v.x; x2[2 * i + 1] = v.y;
            }
            #pragma unroll
            for (int i = 0; i < 8; i++)
                #pragma unroll
                for (int q = 0; q < 8; q++)
                    acc[i][q] = fma2(w2[i], x2[q], acc[i][q]);
        }
        __syncthreads();
    }

    // ---- epilogue: bias, squash, store ----
    float bias[8];
    #pragma unroll
    for (int i = 0; i < 8; i++) bias[i] = g_bias[cg * 8 + i];

    float sq[16];
    #pragma unroll
    for (int p = 0; p < 16; p++) sq[p] = 0.0f;

    #pragma unroll
    for (int i = 0; i < 8; i++) {
        #pragma unroll
        for (int q = 0; q < 8; q++) {
            float y0 = lo32(acc[i][q]) + bias[i];
            float y1 = hi32(acc[i][q]) + bias[i];
            sq[2 * q]     += y0 * y0;
            sq[2 * q + 1] += y1 * y1;
            acc[i][q] = ((unsigned long long)__float_as_uint(y1) << 32)
                      |  (unsigned long long)__float_as_uint(y0);
        }
    }

    __syncthreads();                       // all compute done; reuse smem
    float* red = (float*)smem;             // [128 positions][stride 33]
    #pragma unroll
    for (int p = 0; p < 16; p++)
        red[(pg * 16 + p) * 33 + cg] = sq[p];
    __syncthreads();

    float* scl = red + 128 * 33;
    if (t < 128) {
        float s = 0.0f;
        #pragma unroll
        for (int j = 0; j < 32; j++) s += red[t * 33 + j];
        float norm = sqrtf(s);
        scl[t] = s / ((1.0f + s) * (norm + 1e-8f));   // squash scale
    }
    __syncthreads();

    float* og = out + ((size_t)b * LL + l0) * CC + cg * 8;
    #pragma unroll
    for (int q = 0; q < 8; q++) {
        int p0 = pg * 16 + 2 * q;
        float s0 = scl[p0], s1 = scl[p0 + 1];
        float4 a0, a1, c0, c1;
        a0.x = lo32(acc[0][q]) * s0;  a0.y = lo32(acc[1][q]) * s0;
        a0.z = lo32(acc[2][q]) * s0;  a0.w = lo32(acc[3][q]) * s0;
        a1.x = lo32(acc[4][q]) * s0;  a1.y = lo32(acc[5][q]) * s0;
        a1.z = lo32(acc[6][q]) * s0;  a1.w = lo32(acc[7][q]) * s0;
        c0.x = hi32(acc[0][q]) * s1;  c0.y = hi32(acc[1][q]) * s1;
        c0.z = hi32(acc[2][q]) * s1;  c0.w = hi32(acc[3][q]) * s1;
        c1.x = hi32(acc[4][q]) * s1;  c1.y = hi32(acc[5][q]) * s1;
        c1.z = hi32(acc[6][q]) * s1;  c1.w = hi32(acc[7][q]) * s1;
        float4* o0 = (float4*)(og + (size_t)p0 * CC);
        float4* o1 = (float4*)(og + (size_t)(p0 + 1) * CC);
        o0[0] = a0; o0[1] = a1;
        o1[0] = c0; o1[1] = c1;
    }
}

// ---------------- launch ----------------
extern "C" void kernel_launch(void* const* d_in, const int* in_sizes, int n_in,
                              void* d_out, int out_size) {
    const float* x     = (const float*)d_in[0];
    const float* W     = (const float*)d_in[1];
    const float* b     = (const float*)d_in[2];
    const float* gamma = (const float*)d_in[3];
    const float* beta  = (const float*)d_in[4];
    const float* mean  = (const float*)d_in[5];
    const float* var   = (const float*)d_in[6];
    float* out = (float*)d_out;

    fold_kernel<<<CC, CC>>>(W, b, gamma, beta, mean, var);

    cudaFuncSetAttribute(caps_kernel,
                         cudaFuncAttributeMaxDynamicSharedMemorySize, 81920);
    dim3 grid(LL / TL, BB);
    caps_kernel<<<grid, 256, 81920>>>(x, out);
}

// round 3
// speedup vs baseline: 1.8024x; 1.8024x over previous
#include <cuda_runtime.h>
#include <cuda_bf16.h>
#include <cstdint>

// ------------------------- problem constants -------------------------
#define CC 256
#define LL 8192
#define BB 32
#define TL 128          // positions per CTA
#define KC 64           // K chunk
#define NCHUNK 4

// ------------------------- smem layout (bytes) -----------------------
// W bufs: [buf][hi 32K | lo 32K]
#define WHOFF(b) ((b) * 65536)
#define WLOFF(b) ((b) * 65536 + 32768)
// x bufs: [buf][hi 16K | lo 16K]
#define XHOFF(b) (131072 + (b) * 32768)
#define XLOFF(b) (131072 + (b) * 32768 + 16384)
#define SBIAS    196608
#define SQBUF    197632          // 4 x 128 floats
#define SCALE    199680          // 128 floats
#define SMEM_BYTES 200192

// ------------------------- device scratch ----------------------------
__device__ __align__(16) unsigned g_Wh[NCHUNK * 8192];  // pre-swizzled smem images
__device__ __align__(16) unsigned g_Wl[NCHUNK * 8192];
__device__ float g_bias[CC];

// ------------------------- helpers -----------------------------------
__device__ __forceinline__ uint32_t smem_u32(const void* p) {
    uint32_t a;
    asm("{ .reg .u64 t; cvta.to.shared.u64 t, %1; cvt.u32.u64 %0, t; }"
        : "=r"(a) : "l"(p));
    return a;
}
__device__ __forceinline__ uint32_t swz128(uint32_t off) {
    return off ^ ((off >> 3) & 0x70);
}
__device__ __forceinline__ void cp16(uint32_t dst, const void* src) {
    asm volatile("cp.async.cg.shared.global [%0], [%1], 16;\n" :: "r"(dst), "l"(src));
}
#define CP_COMMIT() asm volatile("cp.async.commit_group;\n" ::: "memory")
#define CP_WAIT1()  asm volatile("cp.async.wait_group 1;\n" ::: "memory")
#define CP_WAIT0()  asm volatile("cp.async.wait_group 0;\n" ::: "memory")

__device__ __forceinline__ void ldsm_x4(uint32_t* r, uint32_t addr) {
    asm volatile("ldmatrix.sync.aligned.m8n8.x4.shared.b16 {%0,%1,%2,%3}, [%4];"
                 : "=r"(r[0]), "=r"(r[1]), "=r"(r[2]), "=r"(r[3]) : "r"(addr));
}
__device__ __forceinline__ void ldsm_x2t(uint32_t* r, uint32_t addr) {
    asm volatile("ldmatrix.sync.aligned.m8n8.x2.trans.shared.b16 {%0,%1}, [%2];"
                 : "=r"(r[0]), "=r"(r[1]) : "r"(addr));
}
__device__ __forceinline__ void mma_bf16(float* d, const uint32_t* a, const uint32_t* b) {
    asm volatile(
        "mma.sync.aligned.m16n8k16.row.col.f32.bf16.bf16.f32 "
        "{%0,%1,%2,%3}, {%4,%5,%6,%7}, {%8,%9}, {%0,%1,%2,%3};"
        : "+f"(d[0]), "+f"(d[1]), "+f"(d[2]), "+f"(d[3])
        : "r"(a[0]), "r"(a[1]), "r"(a[2]), "r"(a[3]), "r"(b[0]), "r"(b[1]));
}
__device__ __forceinline__ unsigned short bfh(float v) {
    return __bfloat16_as_ushort(__float2bfloat16_rn(v));
}

// ------------------------- prep kernel -------------------------------
// Fold BN into W, split bf16 hi/lo, emit pre-swizzled SMEM chunk images:
// chunk kc holds A tile [256 oc][64 c], 128B rows, SW128 swizzle.
__global__ void fold_kernel(const float* __restrict__ W, const float* __restrict__ b,
                            const float* __restrict__ gamma, const float* __restrict__ beta,
                            const float* __restrict__ mean, const float* __restrict__ var) {
    int o = blockIdx.x;
    int j = threadIdx.x;          // c pair: c = 2j
    float inv = gamma[o] * rsqrtf(var[o] + 1e-5f);
    int c = 2 * j;
    float w0 = W[o * CC + c] * inv;
    float w1 = W[o * CC + c + 1] * inv;
    unsigned short h0 = bfh(w0), h1 = bfh(w1);
    float r0 = w0 - __uint_as_float((unsigned)h0 << 16);
    float r1 = w1 - __uint_as_float((unsigned)h1 << 16);
    unsigned short q0 = bfh(r0), q1 = bfh(r1);
    int kc = c >> 6;
    int cl = c & 63;
    unsigned idx = kc * 8192 + (swz128((unsigned)(o * 128 + cl * 2)) >> 2);
    g_Wh[idx] = ((unsigned)h1 << 16) | h0;
    g_Wl[idx] = ((unsigned)q1 << 16) | q0;
    if (j == 0) g_bias[o] = b[o] * inv + beta[o] - mean[o] * inv;
}

// ------------------------- main kernel -------------------------------
extern "C" __global__ void __launch_bounds__(256, 1)
caps_kernel(const float* __restrict__ x, float* __restrict__ out) {
    extern __shared__ char smem[];
    const uint32_t sb = smem_u32(smem);
    const int t    = threadIdx.x;
    const int lane = t & 31;
    const int wid  = t >> 5;
    const int wm   = wid & 3;          // 4 m-warps (oc)
    const int wn   = wid >> 2;         // 2 n-warps (pos)
    const int m0   = wm * 64;
    const int bb   = blockIdx.y;
    const int l0   = blockIdx.x * TL;

    ((float*)(smem + SBIAS))[t] = g_bias[t];

    // precomputed fragment offsets
    uint32_t aoff[4];
    {
        int arow = m0 + (lane & 15);
        #pragma unroll
        for (int i = 0; i < 4; i++) {
            int r = arow + i * 16;
            aoff[i] = (uint32_t)(r * 128) +
                      ((uint32_t)((lane >> 4) << 4) ^ (uint32_t)((r & 7) << 4));
        }
    }
    uint32_t boff[8];
    {
        int rowB = lane & 15, lx = lane & 7;
        #pragma unroll
        for (int j = 0; j < 8; j++)
            boff[j] = (uint32_t)(rowB * 256) + ((uint32_t)((wn * 8 + j) ^ lx) << 4);
    }
    // conversion write base (per thread): c = wid + i*8, pos = lane*4
    const uint32_t convBase = (uint32_t)(wid * 256) +
        ((uint32_t)((lane >> 1) ^ wid) << 4) + (uint32_t)((lane & 1) * 8);

    float acc[4][8][4];
    #pragma unroll
    for (int i = 0; i < 4; i++)
        #pragma unroll
        for (int j = 0; j < 8; j++)
            #pragma unroll
            for (int q = 0; q < 4; q++) acc[i][j][q] = 0.0f;

    // ---- W chunk cp.async (identity copy of pre-swizzled image) ----
    auto issueW = [&](int kc, int buf) {
        uint32_t dh = sb + WHOFF(buf);
        uint32_t dl = sb + WLOFF(buf);
        const char* shh = (const char*)(g_Wh + kc * 8192);
        const char* sll = (const char*)(g_Wl + kc * 8192);
        #pragma unroll
        for (int i = 0; i < 8; i++) {
            int e = t + i * 256;
            cp16(dh + e * 16, shh + e * 16);
            cp16(dl + e * 16, sll + e * 16);
        }
        CP_COMMIT();
    };

    // ---- x LDG prefetch / convert+store ----
    float4 xv[8];
    auto ldg_x = [&](int kc) {
        const float* p = x + ((size_t)bb * CC + (size_t)kc * KC + wid) * LL
                         + l0 + lane * 4;
        #pragma unroll
        for (int i = 0; i < 8; i++)
            xv[i] = __ldg((const float4*)(p + (size_t)i * 8 * LL));
    };
    auto conv_x = [&](int buf) {
        char* xh = smem + XHOFF(buf);
        char* xl = smem + XLOFF(buf);
        #pragma unroll
        for (int i = 0; i < 8; i++) {
            float4 v = xv[i];
            unsigned short hx = bfh(v.x), hy = bfh(v.y), hz = bfh(v.z), hw = bfh(v.w);
            float rx = v.x - __uint_as_float((unsigned)hx << 16);
            float ry = v.y - __uint_as_float((unsigned)hy << 16);
            float rz = v.z - __uint_as_float((unsigned)hz << 16);
            float rw = v.w - __uint_as_float((unsigned)hw << 16);
            unsigned short lx2 = bfh(rx), ly = bfh(ry), lz = bfh(rz), lw = bfh(rw);
            uint32_t off = convBase + (uint32_t)i * 2048;
            *(uint2*)(xh + off) = make_uint2(((unsigned)hy << 16) | hx,
                                             ((unsigned)hw << 16) | hz);
            *(uint2*)(xl + off) = make_uint2(((unsigned)ly << 16) | lx2,
                                             ((unsigned)lw << 16) | lz);
        }
    };

    // ---- mma over one resident chunk (3 split passes x 4 k-steps) ----
    auto do_mma = [&](int buf) {
        #pragma unroll
        for (int p = 0; p < 3; p++) {
            uint32_t Ab = sb + ((p == 1) ? WLOFF(buf) : WHOFF(buf));
            uint32_t Bb = sb + ((p == 2) ? XLOFF(buf) : XHOFF(buf));
            #pragma unroll
            for (int ks = 0; ks < 4; ks++) {
                uint32_t af[4][4], bfr[8][2];
                #pragma unroll
                for (int i = 0; i < 4; i++)
                    ldsm_x4(af[i], Ab + (aoff[i] ^ ((uint32_t)ks << 5)));
                #pragma unroll
                for (int j = 0; j < 8; j++)
                    ldsm_x2t(bfr[j], Bb + boff[j] + ((uint32_t)ks << 12));
                #pragma unroll
                for (int i = 0; i < 4; i++)
                    #pragma unroll
                    for (int j = 0; j < 8; j++)
                        mma_bf16(acc[i][j], af[i], bfr[j]);
            }
        }
    };

    // ---- pipeline ----
    issueW(0, 0);
    ldg_x(0);
    conv_x(0);

    for (int k = 0; k < NCHUNK; k++) {
        __syncthreads();                       // all warps done with buf^1
        if (k < NCHUNK - 1) {
            issueW(k + 1, (k + 1) & 1);
            ldg_x(k + 1);
            CP_WAIT1();
        } else {
            CP_WAIT0();
        }
        __syncthreads();                       // W(k) + x(k) visible
        do_mma(k & 1);
        if (k < NCHUNK - 1) conv_x((k + 1) & 1);
    }

    // ---- epilogue: bias + squash + store ----
    const float* sbias = (const float*)(smem + SBIAS);
    const int gid = lane >> 2;     // row within 16-tile
    const int qid = lane & 3;      // col pair
    const int n0  = wn * 64;

    float sqA[8], sqB[8];
    #pragma unroll
    for (int j = 0; j < 8; j++) { sqA[j] = 0.0f; sqB[j] = 0.0f; }

    #pragma unroll
    for (int i = 0; i < 4; i++) {
        int r0 = m0 + i * 16 + gid;
        float b0 = sbias[r0], b1 = sbias[r0 + 8];
        #pragma unroll
        for (int j = 0; j < 8; j++) {
            float y0 = acc[i][j][0] + b0;
            float y1 = acc[i][j][1] + b0;
            float y2 = acc[i][j][2] + b1;
            float y3 = acc[i][j][3] + b1;
            acc[i][j][0] = y0; acc[i][j][1] = y1;
            acc[i][j][2] = y2; acc[i][j][3] = y3;
            sqA[j] += y0 * y0 + y2 * y2;
            sqB[j] += y1 * y1 + y3 * y3;
        }
    }
    #pragma unroll
    for (int j = 0; j < 8; j++) {
        #pragma unroll
        for (int m = 4; m < 32; m <<= 1) {
            sqA[j] += __shfl_xor_sync(0xffffffffu, sqA[j], m);
            sqB[j] += __shfl_xor_sync(0xffffffffu, sqB[j], m);
        }
    }
    float* sqb = (float*)(smem + SQBUF);
    if (lane < 4) {
        #pragma unroll
        for (int j = 0; j < 8; j++) {
            int col = n0 + j * 8 + lane * 2;
            sqb[wm * 128 + col]     = sqA[j];
            sqb[wm * 128 + col + 1] = sqB[j];
        }
    }
    __syncthreads();
    if (t < 128) {
        float s = sqb[t] + sqb[128 + t] + sqb[256 + t] + sqb[384 + t];
        float n = sqrtf(s);
        ((float*)(smem + SCALE))[t] = s / ((1.0f + s) * (n + 1e-8f));
    }
    __syncthreads();

    const float* scl = (const float*)(smem + SCALE);
    float* og = out + ((size_t)bb * LL + l0) * CC;
    #pragma unroll
    for (int j = 0; j < 8; j++) {
        int c0 = n0 + j * 8 + qid * 2;
        float s0 = scl[c0], s1 = scl[c0 + 1];
        float* p0 = og + (size_t)c0 * CC;
        float* p1 = og + (size_t)(c0 + 1) * CC;
        #pragma unroll
        for (int i = 0; i < 4; i++) {
            int r0 = m0 + i * 16 + gid;
            p0[r0]     = acc[i][j][0] * s0;
            p1[r0]     = acc[i][j][1] * s1;
            p0[r0 + 8] = acc[i][j][2] * s0;
            p1[r0 + 8] = acc[i][j][3] * s1;
        }
    }
}

// ------------------------- launch ------------------------------------
extern "C" void kernel_launch(void* const* d_in, const int* in_sizes, int n_in,
                              void* d_out, int out_size) {
    const float* x     = (const float*)d_in[0];
    const float* W     = (const float*)d_in[1];
    const float* b     = (const float*)d_in[2];
    const float* gamma = (const float*)d_in[3];
    const float* beta  = (const float*)d_in[4];
    const float* mean  = (const float*)d_in[5];
    const float* var   = (const float*)d_in[6];
    float* out = (float*)d_out;

    fold_kernel<<<CC, 128>>>(W, b, gamma, beta, mean, var);

    cudaFuncSetAttribute(caps_kernel,
                         cudaFuncAttributeMaxDynamicSharedMemorySize, SMEM_BYTES);
    dim3 grid(LL / TL, BB);
    caps_kernel<<<grid, 256, SMEM_BYTES>>>(x, out);
}

// round 4
// speedup vs baseline: 3.6319x; 2.0150x over previous
#include <cuda_runtime.h>
#include <cstdint>

// ------------------------- problem constants -------------------------
#define CC 256
#define LL 8192
#define BB 32
#define TL 64            // positions per CTA
#define KC 32            // K chunk
#define NCHUNK 8

// ------------------------- smem layout (bytes) -----------------------
#define WOFF(b)  ((b) * 32768)            // W frag-order tf32: 2 x 32KB
#define XOFF(b)  (65536 + (b) * 9216)     // x: 32 k-rows x 72 floats
#define XSTRIDE  72                       // floats per x row (bank-spread)
#define SBIAS    83968                    // 256 floats
#define SQBUF    84992                    // 4 x 64 floats
#define SCALE    86016                    // 64 floats
#define SMEM_BYTES 86272

// ------------------------- device scratch ----------------------------
// W' in exact A-fragment order: [kc][ks][mb][lane][4 regs] (tf32 bits)
__device__ __align__(16) unsigned g_Wf[CC * CC];
__device__ float g_bias[CC];

// ------------------------- helpers -----------------------------------
__device__ __forceinline__ uint32_t smem_u32(const void* p) {
    uint32_t a;
    asm("{ .reg .u64 t; cvta.to.shared.u64 t, %1; cvt.u32.u64 %0, t; }"
        : "=r"(a) : "l"(p));
    return a;
}
__device__ __forceinline__ uint32_t tf32r(float f) {
    uint32_t u;
    asm("cvt.rna.tf32.f32 %0, %1;" : "=r"(u) : "f"(f));
    return u;
}
__device__ __forceinline__ void cp16(uint32_t dst, const void* src) {
    asm volatile("cp.async.cg.shared.global [%0], [%1], 16;\n" :: "r"(dst), "l"(src));
}
#define CP_COMMIT() asm volatile("cp.async.commit_group;\n" ::: "memory")
#define CP_WAIT1()  asm volatile("cp.async.wait_group 1;\n" ::: "memory")
#define CP_WAIT0()  asm volatile("cp.async.wait_group 0;\n" ::: "memory")

__device__ __forceinline__ void mma_tf32(float* d, const uint32_t* a, const uint32_t* b) {
    asm volatile(
        "mma.sync.aligned.m16n8k8.row.col.f32.tf32.tf32.f32 "
        "{%0,%1,%2,%3}, {%4,%5,%6,%7}, {%8,%9}, {%0,%1,%2,%3};"
        : "+f"(d[0]), "+f"(d[1]), "+f"(d[2]), "+f"(d[3])
        : "r"(a[0]), "r"(a[1]), "r"(a[2]), "r"(a[3]), "r"(b[0]), "r"(b[1]));
}

// ------------------------- prep kernel -------------------------------
// Fold BN into W, convert to tf32 (RN), emit A-fragment-order image.
// Element (o, c) -> g_Wf[((kc*4+ks)*16+mb)*128 + lane*4 + ridx]
__global__ void fold_kernel(const float* __restrict__ W, const float* __restrict__ b,
                            const float* __restrict__ gamma, const float* __restrict__ beta,
                            const float* __restrict__ mean, const float* __restrict__ var) {
    int o = blockIdx.x;
    int c = threadIdx.x;
    float inv = gamma[o] * rsqrtf(var[o] + 1e-5f);
    float w = W[o * CC + c] * inv;
    int kc = c >> 5, ks = (c >> 3) & 3, kl = c & 7;
    int mb = o >> 4, lr = o & 15;
    int lane = (lr & 7) * 4 + (kl & 3);
    int ridx = (lr >> 3) + ((kl >> 2) << 1);
    g_Wf[(((kc << 2) + ks) * 16 + mb) * 128 + lane * 4 + ridx] = tf32r(w);
    if (c == 0) g_bias[o] = b[o] * inv + beta[o] - mean[o] * inv;
}

// ------------------------- main kernel -------------------------------
// 256 threads, 8 warps: wm 0..3 (64 oc each), wn 0..1 (32 pos each).
// 2 CTAs/SM. Tile: 256 oc x 64 pos, K pipelined in 8 chunks of 32.
extern "C" __global__ void __launch_bounds__(256, 2)
caps_kernel(const float* __restrict__ x, float* __restrict__ out) {
    extern __shared__ char smem[];
    const uint32_t sbu = smem_u32(smem);
    const int t    = threadIdx.x;
    const int lane = t & 31;
    const int wid  = t >> 5;
    const int wm   = wid & 3;
    const int wn   = wid >> 2;
    const int m0   = wm * 64;
    const int bb   = blockIdx.y;
    const int l0   = blockIdx.x * TL;

    ((float*)(smem + SBIAS))[t] = g_bias[t];

    const float* xg = x + (size_t)bb * CC * LL + l0;

    float acc[4][4][4];
    #pragma unroll
    for (int i = 0; i < 4; i++)
        #pragma unroll
        for (int j = 0; j < 4; j++)
            #pragma unroll
            for (int q = 0; q < 4; q++) acc[i][j][q] = 0.0f;

    // ---- W chunk via cp.async (identity copy of frag-order image) ----
    auto issueW = [&](int kc, int buf) {
        uint32_t d = sbu + WOFF(buf);
        const char* s = (const char*)(g_Wf + kc * 8192);
        #pragma unroll
        for (int i = 0; i < 8; i++) {
            int e = t + i * 256;
            cp16(d + e * 16, s + e * 16);
        }
        CP_COMMIT();
    };

    // ---- x prefetch (regs) + stage (cvt + STS) ----
    float4 xv[2];
    auto ldg_x = [&](int kc) {
        #pragma unroll
        for (int it = 0; it < 2; it++) {
            int f = t + it * 256;
            int k = f >> 4, p4 = f & 15;
            xv[it] = __ldg((const float4*)(xg + (size_t)(kc * KC + k) * LL + p4 * 4));
        }
    };
    auto stage_x = [&](int buf) {
        #pragma unroll
        for (int it = 0; it < 2; it++) {
            int f = t + it * 256;
            int k = f >> 4, p4 = f & 15;
            uint4 u;
            u.x = tf32r(xv[it].x); u.y = tf32r(xv[it].y);
            u.z = tf32r(xv[it].z); u.w = tf32r(xv[it].w);
            *(uint4*)(smem + XOFF(buf) + (size_t)(k * XSTRIDE + p4 * 4) * 4) = u;
        }
    };

    // ---- mma over one resident chunk: 4 k8-steps ----
    auto do_mma = [&](int buf) {
        const char* Wb = smem + WOFF(buf);
        const char* Xb = smem + XOFF(buf);
        #pragma unroll
        for (int ks = 0; ks < 4; ks++) {
            uint32_t af[4][4], bf[4][2];
            #pragma unroll
            for (int i = 0; i < 4; i++) {
                uint4 v = *(const uint4*)(Wb + ((ks * 16 + wm * 4 + i) * 32 + lane) * 16);
                af[i][0] = v.x; af[i][1] = v.y; af[i][2] = v.z; af[i][3] = v.w;
            }
            #pragma unroll
            for (int j = 0; j < 4; j++) {
                const char* ba = Xb + (size_t)((ks * 8 + (lane & 3)) * XSTRIDE
                                  + wn * 32 + j * 8 + (lane >> 2)) * 4;
                bf[j][0] = *(const uint32_t*)ba;
                bf[j][1] = *(const uint32_t*)(ba + 4 * XSTRIDE * 4);
            }
            #pragma unroll
            for (int i = 0; i < 4; i++)
                #pragma unroll
                for (int j = 0; j < 4; j++)
                    mma_tf32(acc[i][j], af[i], bf[j]);
        }
    };

    // ---- pipeline ----
    issueW(0, 0);
    ldg_x(0);
    stage_x(0);

    for (int k = 0; k < NCHUNK; k++) {
        __syncthreads();                     // mma(k-1) done: bufs k&1^1 reusable
        if (k < NCHUNK - 1) {
            issueW(k + 1, (k + 1) & 1);
            ldg_x(k + 1);
            CP_WAIT1();
        } else {
            CP_WAIT0();
        }
        __syncthreads();                     // W(k), x(k) visible
        do_mma(k & 1);
        if (k < NCHUNK - 1) stage_x((k + 1) & 1);
    }

    // ---- epilogue: bias + squash + store ----
    const float* sbias = (const float*)(smem + SBIAS);
    const int gid = lane >> 2;     // row-within-16 group
    const int qid = lane & 3;      // position pair
    const int n0  = wn * 32;

    float sqA[4], sqB[4];
    #pragma unroll
    for (int j = 0; j < 4; j++) { sqA[j] = 0.0f; sqB[j] = 0.0f; }

    #pragma unroll
    for (int i = 0; i < 4; i++) {
        int r0 = m0 + i * 16 + gid;
        float b0 = sbias[r0], b1 = sbias[r0 + 8];
        #pragma unroll
        for (int j = 0; j < 4; j++) {
            float y0 = acc[i][j][0] + b0;
            float y1 = acc[i][j][1] + b0;
            float y2 = acc[i][j][2] + b1;
            float y3 = acc[i][j][3] + b1;
            acc[i][j][0] = y0; acc[i][j][1] = y1;
            acc[i][j][2] = y2; acc[i][j][3] = y3;
            sqA[j] += y0 * y0 + y2 * y2;
            sqB[j] += y1 * y1 + y3 * y3;
        }
    }
    #pragma unroll
    for (int j = 0; j < 4; j++) {
        #pragma unroll
        for (int m = 4; m < 32; m <<= 1) {
            sqA[j] += __shfl_xor_sync(0xffffffffu, sqA[j], m);
            sqB[j] += __shfl_xor_sync(0xffffffffu, sqB[j], m);
        }
    }
    float* sqb = (float*)(smem + SQBUF);
    if (lane < 4) {
        #pragma unroll
        for (int j = 0; j < 4; j++) {
            int col = n0 + j * 8 + lane * 2;
            sqb[wm * 64 + col]     = sqA[j];
            sqb[wm * 64 + col + 1] = sqB[j];
        }
    }
    __syncthreads();
    if (t < 64) {
        float s = sqb[t] + sqb[64 + t] + sqb[128 + t] + sqb[192 + t];
        float n = sqrtf(s);
        ((float*)(smem + SCALE))[t] = s / ((1.0f + s) * (n + 1e-8f));
    }
    __syncthreads();

    const float* scl = (const float*)(smem + SCALE);
    float* og = out + ((size_t)bb * LL + l0) * CC;
    #pragma unroll
    for (int j = 0; j < 4; j++) {
        int c0 = n0 + j * 8 + qid * 2;       // position
        float s0 = scl[c0], s1 = scl[c0 + 1];
        float* p0 = og + (size_t)c0 * CC;
        float* p1 = og + (size_t)(c0 + 1) * CC;
        #pragma unroll
        for (int i = 0; i < 4; i++) {
            int r0 = m0 + i * 16 + gid;      // channel
            p0[r0]     = acc[i][j][0] * s0;
            p1[r0]     = acc[i][j][1] * s1;
            p0[r0 + 8] = acc[i][j][2] * s0;
            p1[r0 + 8] = acc[i][j][3] * s1;
        }
    }
}

// ------------------------- launch ------------------------------------
extern "C" void kernel_launch(void* const* d_in, const int* in_sizes, int n_in,
                              void* d_out, int out_size) {
    const float* x     = (const float*)d_in[0];
    const float* W     = (const float*)d_in[1];
    const float* b     = (const float*)d_in[2];
    const float* gamma = (const float*)d_in[3];
    const float* beta  = (const float*)d_in[4];
    const float* mean  = (const float*)d_in[5];
    const float* var   = (const float*)d_in[6];
    float* out = (float*)d_out;

    fold_kernel<<<CC, CC>>>(W, b, gamma, beta, mean, var);

    cudaFuncSetAttribute(caps_kernel,
                         cudaFuncAttributeMaxDynamicSharedMemorySize, SMEM_BYTES);
    dim3 grid(LL / TL, BB);
    caps_kernel<<<grid, 256, SMEM_BYTES>>>(x, out);
}

// round 5
// speedup vs baseline: 3.6784x; 1.0128x over previous
#include <cuda_runtime.h>
#include <cstdint>

// ------------------------- problem constants -------------------------
#define CC 256
#define LL 8192
#define BB 32
#define TL 64            // positions per CTA
#define KC 32            // K chunk
#define NCHUNK 8

// ------------------------- smem layout (bytes) -----------------------
#define WOFF(b)  ((b) * 32768)            // W frag-order tf32: 2 x 32KB
#define XOFF(b)  (65536 + (b) * 9216)     // x raw fp32: 32 rows x 72 floats
#define XSTRIDE  72                       // floats per x row (banks 8a+b: conflict-free)
#define SBIAS    83968                    // 256 floats
#define SQBUF    84992                    // 4 x 64 floats
#define SCALE    86016                    // 64 floats
#define SMEM_BYTES 86272

// ------------------------- device scratch ----------------------------
// W' in exact A-fragment order: [kc][ks][mb][lane][4 regs] (tf32 bits)
__device__ __align__(16) unsigned g_Wf[CC * CC];
__device__ float g_bias[CC];

// ------------------------- helpers -----------------------------------
__device__ __forceinline__ uint32_t smem_u32(const void* p) {
    uint32_t a;
    asm("{ .reg .u64 t; cvta.to.shared.u64 t, %1; cvt.u32.u64 %0, t; }"
        : "=r"(a) : "l"(p));
    return a;
}
__device__ __forceinline__ uint32_t tf32r(float f) {
    uint32_t u;
    asm("cvt.rna.tf32.f32 %0, %1;" : "=r"(u) : "f"(f));
    return u;
}
__device__ __forceinline__ void cp16(uint32_t dst, const void* src) {
    asm volatile("cp.async.cg.shared.global [%0], [%1], 16;\n" :: "r"(dst), "l"(src));
}
#define CP_COMMIT() asm volatile("cp.async.commit_group;\n" ::: "memory")
#define CP_WAIT1()  asm volatile("cp.async.wait_group 1;\n" ::: "memory")
#define CP_WAIT0()  asm volatile("cp.async.wait_group 0;\n" ::: "memory")

__device__ __forceinline__ void mma_tf32(float* d, const uint32_t* a, const uint32_t* b) {
    asm volatile(
        "mma.sync.aligned.m16n8k8.row.col.f32.tf32.tf32.f32 "
        "{%0,%1,%2,%3}, {%4,%5,%6,%7}, {%8,%9}, {%0,%1,%2,%3};"
        : "+f"(d[0]), "+f"(d[1]), "+f"(d[2]), "+f"(d[3])
        : "r"(a[0]), "r"(a[1]), "r"(a[2]), "r"(a[3]), "r"(b[0]), "r"(b[1]));
}

// ------------------------- prep kernel -------------------------------
// Fold BN into W, convert to tf32 (RNA), emit A-fragment-order image.
__global__ void fold_kernel(const float* __restrict__ W, const float* __restrict__ b,
                            const float* __restrict__ gamma, const float* __restrict__ beta,
                            const float* __restrict__ mean, const float* __restrict__ var) {
    int o = blockIdx.x;
    int c = threadIdx.x;
    float inv = gamma[o] * rsqrtf(var[o] + 1e-5f);
    float w = W[o * CC + c] * inv;
    int kc = c >> 5, ks = (c >> 3) & 3, kl = c & 7;
    int mb = o >> 4, lr = o & 15;
    int lane = (lr & 7) * 4 + (kl & 3);
    int ridx = (lr >> 3) + ((kl >> 2) << 1);
    g_Wf[(((kc << 2) + ks) * 16 + mb) * 128 + lane * 4 + ridx] = tf32r(w);
    if (c == 0) g_bias[o] = b[o] * inv + beta[o] - mean[o] * inv;
}

// ------------------------- main kernel -------------------------------
// 256 threads, 8 warps: wm 0..3 (64 oc each), wn 0..1 (32 pos each).
// 2 CTAs/SM. Tile: 256 oc x 64 pos, K pipelined in 8 chunks of 32.
// x arrives raw fp32 via cp.async; tf32 convert happens on B-frag registers.
extern "C" __global__ void __launch_bounds__(256, 2)
caps_kernel(const float* __restrict__ x, float* __restrict__ out) {
    extern __shared__ char smem[];
    const uint32_t sbu = smem_u32(smem);
    const int t    = threadIdx.x;
    const int lane = t & 31;
    const int wid  = t >> 5;
    const int wm   = wid & 3;
    const int wn   = wid >> 2;
    const int m0   = wm * 64;
    const int bb   = blockIdx.y;
    const int l0   = blockIdx.x * TL;

    ((float*)(smem + SBIAS))[t] = g_bias[t];

    const float* xg = x + (size_t)bb * CC * LL + l0;

    float acc[4][4][4];
    #pragma unroll
    for (int i = 0; i < 4; i++)
        #pragma unroll
        for (int j = 0; j < 4; j++)
            #pragma unroll
            for (int q = 0; q < 4; q++) acc[i][j][q] = 0.0f;

    // ---- one K-chunk: W (frag-order image) + raw x via cp.async ----
    auto issue = [&](int kc, int buf) {
        uint32_t dW = sbu + WOFF(buf);
        const char* sW = (const char*)(g_Wf + kc * 8192);
        #pragma unroll
        for (int i = 0; i < 8; i++) {
            int e = t + i * 256;
            cp16(dW + e * 16, sW + e * 16);
        }
        uint32_t dX = sbu + XOFF(buf);
        #pragma unroll
        for (int i = 0; i < 2; i++) {
            int e = t + i * 256;          // 512 chunks: 32 rows x 16 x 16B
            int r = e >> 4, c16 = e & 15;
            cp16(dX + (uint32_t)(r * XSTRIDE + c16 * 4) * 4,
                 xg + (size_t)(kc * KC + r) * LL + c16 * 4);
        }
        CP_COMMIT();
    };

    // ---- mma over one resident chunk: 4 k8-steps ----
    const uint32_t bcol = (uint32_t)(wn * 32 + (lane >> 2));  // position within tile
    const uint32_t brow = (uint32_t)(lane & 3);
    auto do_mma = [&](int buf) {
        const char* Wb = smem + WOFF(buf);
        const char* Xb = smem + XOFF(buf) + (size_t)(brow * XSTRIDE + bcol) * 4;
        #pragma unroll
        for (int ks = 0; ks < 4; ks++) {
            uint32_t af[4][4], bf[4][2];
            #pragma unroll
            for (int i = 0; i < 4; i++) {
                uint4 v = *(const uint4*)(Wb + ((ks * 16 + wm * 4 + i) * 32 + lane) * 16);
                af[i][0] = v.x; af[i][1] = v.y; af[i][2] = v.z; af[i][3] = v.w;
            }
            #pragma unroll
            for (int j = 0; j < 4; j++) {
                const char* ba = Xb + (size_t)(ks * 8 * XSTRIDE + j * 8) * 4;
                float b0 = *(const float*)ba;
                float b1 = *(const float*)(ba + 4 * XSTRIDE * 4);
                bf[j][0] = tf32r(b0);
                bf[j][1] = tf32r(b1);
            }
            #pragma unroll
            for (int i = 0; i < 4; i++)
                #pragma unroll
                for (int j = 0; j < 4; j++)
                    mma_tf32(acc[i][j], af[i], bf[j]);
        }
    };

    // ---- pipeline ----
    issue(0, 0);

    for (int k = 0; k < NCHUNK; k++) {
        __syncthreads();                     // mma(k-1) done: buf (k+1)&1 reusable
        if (k < NCHUNK - 1) {
            issue(k + 1, (k + 1) & 1);
            CP_WAIT1();
        } else {
            CP_WAIT0();
        }
        __syncthreads();                     // W(k), x(k) visible to all warps
        do_mma(k & 1);
    }

    // ---- epilogue: bias + squash + store ----
    const float* sbias = (const float*)(smem + SBIAS);
    const int gid = lane >> 2;     // row-within-16 group
    const int qid = lane & 3;      // position pair
    const int n0  = wn * 32;

    float sqA[4], sqB[4];
    #pragma unroll
    for (int j = 0; j < 4; j++) { sqA[j] = 0.0f; sqB[j] = 0.0f; }

    #pragma unroll
    for (int i = 0; i < 4; i++) {
        int r0 = m0 + i * 16 + gid;
        float b0 = sbias[r0], b1 = sbias[r0 + 8];
        #pragma unroll
        for (int j = 0; j < 4; j++) {
            float y0 = acc[i][j][0] + b0;
            float y1 = acc[i][j][1] + b0;
            float y2 = acc[i][j][2] + b1;
            float y3 = acc[i][j][3] + b1;
            acc[i][j][0] = y0; acc[i][j][1] = y1;
            acc[i][j][2] = y2; acc[i][j][3] = y3;
            sqA[j] += y0 * y0 + y2 * y2;
            sqB[j] += y1 * y1 + y3 * y3;
        }
    }
    #pragma unroll
    for (int j = 0; j < 4; j++) {
        #pragma unroll
        for (int m = 4; m < 32; m <<= 1) {
            sqA[j] += __shfl_xor_sync(0xffffffffu, sqA[j], m);
            sqB[j] += __shfl_xor_sync(0xffffffffu, sqB[j], m);
        }
    }
    float* sqb = (float*)(smem + SQBUF);
    if (lane < 4) {
        #pragma unroll
        for (int j = 0; j < 4; j++) {
            int col = n0 + j * 8 + lane * 2;
            sqb[wm * 64 + col]     = sqA[j];
            sqb[wm * 64 + col + 1] = sqB[j];
        }
    }
    __syncthreads();
    if (t < 64) {
        float s = sqb[t] + sqb[64 + t] + sqb[128 + t] + sqb[192 + t];
        float n = sqrtf(s);
        ((float*)(smem + SCALE))[t] = s / ((1.0f + s) * (n + 1e-8f));
    }
    __syncthreads();

    const float* scl = (const float*)(smem + SCALE);
    float* og = out + ((size_t)bb * LL + l0) * CC;
    #pragma unroll
    for (int j = 0; j < 4; j++) {
        int c0 = n0 + j * 8 + qid * 2;       // position
        float s0 = scl[c0], s1 = scl[c0 + 1];
        float* p0 = og + (size_t)c0 * CC;
        float* p1 = og + (size_t)(c0 + 1) * CC;
        #pragma unroll
        for (int i = 0; i < 4; i++) {
            int r0 = m0 + i * 16 + gid;      // channel
            p0[r0]     = acc[i][j][0] * s0;
            p1[r0]     = acc[i][j][1] * s1;
            p0[r0 + 8] = acc[i][j][2] * s0;
            p1[r0 + 8] = acc[i][j][3] * s1;
        }
    }
}

// ------------------------- launch ------------------------------------
extern "C" void kernel_launch(void* const* d_in, const int* in_sizes, int n_in,
                              void* d_out, int out_size) {
    const float* x     = (const float*)d_in[0];
    const float* W     = (const float*)d_in[1];
    const float* b     = (const float*)d_in[2];
    const float* gamma = (const float*)d_in[3];
    const float* beta  = (const float*)d_in[4];
    const float* mean  = (const float*)d_in[5];
    const float* var   = (const float*)d_in[6];
    float* out = (float*)d_out;

    fold_kernel<<<CC, CC>>>(W, b, gamma, beta, mean, var);

    cudaFuncSetAttribute(caps_kernel,
                         cudaFuncAttributeMaxDynamicSharedMemorySize, SMEM_BYTES);
    dim3 grid(LL / TL, BB);
    caps_kernel<<<grid, 256, SMEM_BYTES>>>(x, out);
}

// round 6
// speedup vs baseline: 5.2665x; 1.4317x over previous
#include <cuda_runtime.h>
#include <cuda_fp16.h>
#include <cstdint>

// ------------------------- problem constants -------------------------
#define CC 256
#define LL 8192
#define BB 32
#define TL 64            // positions per CTA
#define KC 32            // K chunk
#define NCHUNK 8
#define NSTAGE 3

// ------------------------- smem layout (bytes) -----------------------
#define WOFF(s)  ((s) * 16384)            // W fp16 frag-order: 3 x 16KB
#define XOFF(s)  (49152 + (s) * 4096)     // x fp16: 32 k-rows x 128B (xor-swizzled)
#define SBIAS    61440                    // 256 floats
#define SQBUF    62464                    // 4 x 64 floats
#define SCALE    63488                    // 64 floats
#define SMEM_BYTES 63744

// ------------------------- device scratch ----------------------------
// W' fp16 pairs in exact A-fragment order:
// idx = (((kc*2+ks)*16 + mb)*32 + lane)*4 + reg   (each u32 = 2 fp16, k-pair)
__device__ __align__(16) unsigned g_Wf[CC * CC / 2];
__device__ float g_bias[CC];

// ------------------------- helpers -----------------------------------
__device__ __forceinline__ uint32_t smem_u32(const void* p) {
    uint32_t a;
    asm("{ .reg .u64 t; cvta.to.shared.u64 t, %1; cvt.u32.u64 %0, t; }"
        : "=r"(a) : "l"(p));
    return a;
}
__device__ __forceinline__ uint32_t pkh2(float a, float b) {
    __half2 h = __floats2half2_rn(a, b);
    return *reinterpret_cast<uint32_t*>(&h);
}
__device__ __forceinline__ void cp16(uint32_t dst, const void* src) {
    asm volatile("cp.async.cg.shared.global [%0], [%1], 16;\n" :: "r"(dst), "l"(src));
}
#define CP_COMMIT() asm volatile("cp.async.commit_group;\n" ::: "memory")

__device__ __forceinline__ void ldsm_x2t(uint32_t* r, uint32_t addr) {
    asm volatile("ldmatrix.sync.aligned.m8n8.x2.trans.shared.b16 {%0,%1}, [%2];"
                 : "=r"(r[0]), "=r"(r[1]) : "r"(addr));
}
__device__ __forceinline__ void mma_f16(float* d, const uint32_t* a, const uint32_t* b) {
    asm volatile(
        "mma.sync.aligned.m16n8k16.row.col.f32.f16.f16.f32 "
        "{%0,%1,%2,%3}, {%4,%5,%6,%7}, {%8,%9}, {%0,%1,%2,%3};"
        : "+f"(d[0]), "+f"(d[1]), "+f"(d[2]), "+f"(d[3])
        : "r"(a[0]), "r"(a[1]), "r"(a[2]), "r"(a[3]), "r"(b[0]), "r"(b[1]));
}

// ------------------------- prep kernel -------------------------------
// Fold BN into W, convert fp16, emit A-fragment-order image (k-pairs packed).
__global__ void fold_kernel(const float* __restrict__ W, const float* __restrict__ b,
                            const float* __restrict__ gamma, const float* __restrict__ beta,
                            const float* __restrict__ mean, const float* __restrict__ var) {
    int o = blockIdx.x;
    int j = threadIdx.x;          // c pair: c = 2j, 2j+1
    float inv = gamma[o] * rsqrtf(var[o] + 1e-5f);
    int c = 2 * j;
    float w0 = W[o * CC + c] * inv;
    float w1 = W[o * CC + c + 1] * inv;
    int kc = c >> 5;              // 32-chunk
    int ks = (c >> 4) & 1;        // k16 step within chunk
    int kl = c & 15;              // k within 16 (even)
    int mb = o >> 4;
    int lane = (o & 7) * 4 + ((kl >> 1) & 3);
    int reg  = ((o >> 3) & 1) + 2 * (kl >> 3);
    g_Wf[(((kc * 2 + ks) * 16 + mb) * 32 + lane) * 4 + reg] = pkh2(w0, w1);
    if (j == 0) g_bias[o] = b[o] * inv + beta[o] - mean[o] * inv;
}

// ------------------------- main kernel -------------------------------
// 256 threads, 8 warps: wm 0..3 (64 oc), wn 0..1 (32 pos). 2 CTAs/SM.
// Tile 256 oc x 64 pos; K in 8 chunks of 32; 3-stage pipeline, 1 barrier/chunk.
extern "C" __global__ void __launch_bounds__(256, 2)
caps_kernel(const float* __restrict__ x, float* __restrict__ out) {
    extern __shared__ char smem[];
    const uint32_t sbu = smem_u32(smem);
    const int t    = threadIdx.x;
    const int lane = t & 31;
    const int wid  = t >> 5;
    const int wm   = wid & 3;
    const int wn   = wid >> 2;
    const int m0   = wm * 64;
    const int bb   = blockIdx.y;
    const int l0   = blockIdx.x * TL;

    ((float*)(smem + SBIAS))[t] = g_bias[t];

    const float* xg = x + (size_t)bb * CC * LL + l0;

    float acc[4][4][4];
    #pragma unroll
    for (int i = 0; i < 4; i++)
        #pragma unroll
        for (int j = 0; j < 4; j++)
            #pragma unroll
            for (int q = 0; q < 4; q++) acc[i][j][q] = 0.0f;

    // ---- W chunk via cp.async (identity copy of fp16 frag image) ----
    auto issueW = [&](int kc, int st) {
        uint32_t d = sbu + WOFF(st);
        const char* s = (const char*)(g_Wf + kc * 4096);
        #pragma unroll
        for (int i = 0; i < 4; i++) {
            int e = t + i * 256;
            cp16(d + e * 16, s + e * 16);
        }
        CP_COMMIT();
    };

    // ---- x: LDG prefetch (regs), then cvt+STS after mma ----
    const int xk = t >> 3;      // k row 0..31
    const int xp = t & 7;       // 8-pos group
    const uint32_t xsts = (uint32_t)(xk * 128 + ((xp ^ (xk & 7)) << 4));
    float4 xa, xb2;
    auto ldg_x = [&](int kc) {
        const float* s = xg + (size_t)(kc * KC + xk) * LL + xp * 8;
        xa  = __ldg((const float4*)s);
        xb2 = __ldg((const float4*)(s + 4));
    };
    auto stage_x = [&](int st) {
        uint4 u;
        u.x = pkh2(xa.x, xa.y);  u.y = pkh2(xa.z, xa.w);
        u.z = pkh2(xb2.x, xb2.y); u.w = pkh2(xb2.z, xb2.w);
        *(uint4*)(smem + XOFF(st) + xsts) = u;
    };

    // ---- mma over one resident chunk: 2 k16-steps ----
    auto do_mma = [&](int st) {
        const char* Wb = smem + WOFF(st);
        const uint32_t Xb = sbu + XOFF(st);
        #pragma unroll
        for (int ks = 0; ks < 2; ks++) {
            uint32_t af[4][4], bf[4][2];
            #pragma unroll
            for (int i = 0; i < 4; i++) {
                uint4 v = *(const uint4*)(Wb + ((ks * 16 + wm * 4 + i) * 32 + lane) * 16);
                af[i][0] = v.x; af[i][1] = v.y; af[i][2] = v.z; af[i][3] = v.w;
            }
            #pragma unroll
            for (int j = 0; j < 4; j++)
                ldsm_x2t(bf[j], Xb + (uint32_t)((ks * 16 + (lane & 15)) * 128
                                   + (((wn * 4 + j) ^ (lane & 7)) << 4)));
            #pragma unroll
            for (int i = 0; i < 4; i++)
                #pragma unroll
                for (int j = 0; j < 4; j++)
                    mma_f16(acc[i][j], af[i], bf[j]);
        }
    };

    // ---- 3-stage pipeline, one barrier per chunk ----
    issueW(0, 0); ldg_x(0); stage_x(0);
    issueW(1, 1); ldg_x(1); stage_x(1);

    for (int k = 0; k < NCHUNK; k++) {
        __syncthreads();                       // all warps done mma(k-1)
        if (k < NCHUNK - 2) {
            issueW(k + 2, (k + 2) % NSTAGE);
            ldg_x(k + 2);
            asm volatile("cp.async.wait_group 2;\n" ::: "memory");
        } else if (k == NCHUNK - 2) {
            asm volatile("cp.async.wait_group 1;\n" ::: "memory");
        } else {
            asm volatile("cp.async.wait_group 0;\n" ::: "memory");
        }
        __syncthreads();                       // W(k) visible (cp.async) + x(k) STS
        do_mma(k % NSTAGE);
        if (k < NCHUNK - 2) stage_x((k + 2) % NSTAGE);
    }

    // ---- epilogue: bias + squash + store ----
    const float* sbias = (const float*)(smem + SBIAS);
    const int gid = lane >> 2;     // row-within-16 group
    const int qid = lane & 3;      // position pair
    const int n0  = wn * 32;

    float sqA[4], sqB[4];
    #pragma unroll
    for (int j = 0; j < 4; j++) { sqA[j] = 0.0f; sqB[j] = 0.0f; }

    #pragma unroll
    for (int i = 0; i < 4; i++) {
        int r0 = m0 + i * 16 + gid;
        float b0 = sbias[r0], b1 = sbias[r0 + 8];
        #pragma unroll
        for (int j = 0; j < 4; j++) {
            float y0 = acc[i][j][0] + b0;
            float y1 = acc[i][j][1] + b0;
            float y2 = acc[i][j][2] + b1;
            float y3 = acc[i][j][3] + b1;
            acc[i][j][0] = y0; acc[i][j][1] = y1;
            acc[i][j][2] = y2; acc[i][j][3] = y3;
            sqA[j] += y0 * y0 + y2 * y2;
            sqB[j] += y1 * y1 + y3 * y3;
        }
    }
    #pragma unroll
    for (int j = 0; j < 4; j++) {
        #pragma unroll
        for (int m = 4; m < 32; m <<= 1) {
            sqA[j] += __shfl_xor_sync(0xffffffffu, sqA[j], m);
            sqB[j] += __shfl_xor_sync(0xffffffffu, sqB[j], m);
        }
    }
    float* sqb = (float*)(smem + SQBUF);
    if (lane < 4) {
        #pragma unroll
        for (int j = 0; j < 4; j++) {
            int col = n0 + j * 8 + lane * 2;
            sqb[wm * 64 + col]     = sqA[j];
            sqb[wm * 64 + col + 1] = sqB[j];
        }
    }
    __syncthreads();
    if (t < 64) {
        float s = sqb[t] + sqb[64 + t] + sqb[128 + t] + sqb[192 + t];
        float n = sqrtf(s);
        ((float*)(smem + SCALE))[t] = s / ((1.0f + s) * (n + 1e-8f));
    }
    __syncthreads();

    const float* scl = (const float*)(smem + SCALE);
    float* og = out + ((size_t)bb * LL + l0) * CC;
    #pragma unroll
    for (int j = 0; j < 4; j++) {
        int c0 = n0 + j * 8 + qid * 2;       // position
        float s0 = scl[c0], s1 = scl[c0 + 1];
        float* p0 = og + (size_t)c0 * CC;
        float* p1 = og + (size_t)(c0 + 1) * CC;
        #pragma unroll
        for (int i = 0; i < 4; i++) {
            int r0 = m0 + i * 16 + gid;      // channel
            p0[r0]     = acc[i][j][0] * s0;
            p1[r0]     = acc[i][j][1] * s1;
            p0[r0 + 8] = acc[i][j][2] * s0;
            p1[r0 + 8] = acc[i][j][3] * s1;
        }
    }
}

// ------------------------- launch ------------------------------------
extern "C" void kernel_launch(void* const* d_in, const int* in_sizes, int n_in,
                              void* d_out, int out_size) {
    const float* x     = (const float*)d_in[0];
    const float* W     = (const float*)d_in[1];
    const float* b     = (const float*)d_in[2];
    const float* gamma = (const float*)d_in[3];
    const float* beta  = (const float*)d_in[4];
    const float* mean  = (const float*)d_in[5];
    const float* var   = (const float*)d_in[6];
    float* out = (float*)d_out;

    fold_kernel<<<CC, 128>>>(W, b, gamma, beta, mean, var);

    cudaFuncSetAttribute(caps_kernel,
                         cudaFuncAttributeMaxDynamicSharedMemorySize, SMEM_BYTES);
    dim3 grid(LL / TL, BB);
    caps_kernel<<<grid, 256, SMEM_BYTES>>>(x, out);
}